// round 4
// baseline (speedup 1.0000x reference)
#include <cuda_runtime.h>
#include <math.h>

#define T_DIM 256
#define S_DIM 2048
#define C_DIM 128
#define G3    192
#define L_DIM 64

typedef unsigned long long ull;

// Scratch gx = h_proj @ W_ih^T + b_ih, layout [t][j][s]
__device__ float g_gx[(size_t)T_DIM * G3 * S_DIM];

// ---- packed f32x2 helpers ----
__device__ __forceinline__ ull dup2(float x) {
    ull r; asm("mov.b64 %0, {%1, %1};" : "=l"(r) : "f"(x)); return r;
}
__device__ __forceinline__ ull pack2(float x, float y) {
    ull r; asm("mov.b64 %0, {%1, %2};" : "=l"(r) : "f"(x), "f"(y)); return r;
}
__device__ __forceinline__ void fma2(ull& d, ull a, ull b) {
    asm("fma.rn.f32x2 %0, %1, %2, %0;" : "+l"(d) : "l"(a), "l"(b));
}
__device__ __forceinline__ float2 unpk(ull v) {
    float2 f; asm("mov.b64 {%0, %1}, %2;" : "=f"(f.x), "=f"(f.y) : "l"(v)); return f;
}

// ---------------------------------------------------------------------------
// Phase 1: MLP (128->32->64, LeakyReLU) + gx projection (64->192), f32x2.
// (unchanged — ~630us)
// ---------------------------------------------------------------------------
__global__ void __launch_bounds__(256, 2) mlp_gx_kernel(
    const float* __restrict__ x,
    const float* __restrict__ W1, const float* __restrict__ b1,
    const float* __restrict__ W2, const float* __restrict__ b2,
    const float* __restrict__ Wih, const float* __restrict__ bih)
{
    extern __shared__ float sm[];
    float* W1s  = sm;                 // 4096
    float* W2s  = W1s  + 4096;        // 2048
    float* WihT = W2s  + 2048;        // 64*196 = 12544
    float* b1s  = WihT + 12544;       // 32
    float* b2s  = b1s  + 32;          // 64
    float* bihs = b2s  + 64;          // 192
    float* h1s  = bihs + 192;         // 32*256 = 8192  [k][tid]
    // total 27168 floats = 108672 B -> 2 blocks/SM

    const int tid = threadIdx.x;

    for (int i = tid; i < 4096; i += 256) W1s[i] = W1[i];
    for (int i = tid; i < 2048; i += 256) W2s[i] = W2[i];
    for (int i = tid; i < 12288; i += 256) {
        int j = i >> 6, k = i & 63;           // Wih is (192,64) row-major
        WihT[k * 196 + j] = Wih[i];
    }
    if (tid < 32)  b1s[tid] = b1[tid];
    if (tid < 64)  b2s[tid] = b2[tid];
    if (tid < 192) bihs[tid] = bih[tid];
    __syncthreads();

    const int row = blockIdx.x * 256 + tid;
    const int t = row >> 11;
    const int s = row & 2047;

    // ---- GEMM1: 128 -> 32 ----
    ull a1[16];
    {
        const ull* bp = reinterpret_cast<const ull*>(b1s);
        #pragma unroll
        for (int c = 0; c < 16; c++) a1[c] = bp[c];
    }
    const float4* xv = reinterpret_cast<const float4*>(x + (size_t)row * C_DIM);
    #pragma unroll 4
    for (int k4 = 0; k4 < 32; k4++) {
        float4 xq = __ldg(&xv[k4]);
        float xr[4] = {xq.x, xq.y, xq.z, xq.w};
        #pragma unroll
        for (int kk = 0; kk < 4; kk++) {
            ull xd = dup2(xr[kk]);
            const ulonglong2* w = reinterpret_cast<const ulonglong2*>(&W1s[(k4*4+kk) * 32]);
            #pragma unroll
            for (int c2 = 0; c2 < 8; c2++) {
                ulonglong2 wv = w[c2];
                fma2(a1[c2*2+0], xd, wv.x);
                fma2(a1[c2*2+1], xd, wv.y);
            }
        }
    }
    #pragma unroll
    for (int c = 0; c < 16; c++) {
        float2 f = unpk(a1[c]);
        h1s[(2*c+0) * 256 + tid] = fmaxf(f.x, 0.01f * f.x);
        h1s[(2*c+1) * 256 + tid] = fmaxf(f.y, 0.01f * f.y);
    }

    // ---- GEMM2: 32 -> 64 ----
    ull a2[32];
    {
        const ull* bp = reinterpret_cast<const ull*>(b2s);
        #pragma unroll
        for (int c = 0; c < 32; c++) a2[c] = bp[c];
    }
    #pragma unroll 4
    for (int k = 0; k < 32; k++) {
        ull hd = dup2(h1s[k * 256 + tid]);
        const ulonglong2* w = reinterpret_cast<const ulonglong2*>(&W2s[k * 64]);
        #pragma unroll
        for (int c2 = 0; c2 < 16; c2++) {
            ulonglong2 wv = w[c2];
            fma2(a2[c2*2+0], hd, wv.x);
            fma2(a2[c2*2+1], hd, wv.y);
        }
    }
    float h2[64];
    #pragma unroll
    for (int c = 0; c < 32; c++) {
        float2 f = unpk(a2[c]);
        h2[2*c+0] = fmaxf(f.x, 0.01f * f.x);
        h2[2*c+1] = fmaxf(f.y, 0.01f * f.y);
    }

    // ---- GEMM3: 64 -> 192 in 6 chunks of 32 ----
    float* gbase = &g_gx[(size_t)t * G3 * S_DIM + s];
    #pragma unroll 1
    for (int ch = 0; ch < 6; ch++) {
        const int j0 = ch * 32;
        ull acc[16];
        const ull* bp = reinterpret_cast<const ull*>(&bihs[j0]);
        #pragma unroll
        for (int c = 0; c < 16; c++) acc[c] = bp[c];

        #pragma unroll
        for (int k = 0; k < 64; k++) {
            ull hd = dup2(h2[k]);
            const ulonglong2* w = reinterpret_cast<const ulonglong2*>(&WihT[k * 196 + j0]);
            #pragma unroll
            for (int c2 = 0; c2 < 8; c2++) {
                ulonglong2 wv = w[c2];
                fma2(acc[c2*2+0], hd, wv.x);
                fma2(acc[c2*2+1], hd, wv.y);
            }
        }
        float* gd = gbase + (size_t)j0 * S_DIM;
        #pragma unroll
        for (int c = 0; c < 16; c++) {
            float2 f = unpk(acc[c]);
            gd[(size_t)(2*c+0) * S_DIM] = f.x;
            gd[(size_t)(2*c+1) * S_DIM] = f.y;
        }
    }
}

// ---------------------------------------------------------------------------
// Phase 2: GRU. 128 blocks x 768 threads (24 warps/SM), 16 stocks/block.
// Thread = (gj 0..191, sp 0..1, kq 0..1): tid = gj*4 + sp*2 + kq.
// k-reduction split in half (kq) -> 2x warps; weights from smem (pre-dup'd
// ull), ~50 regs/thread. gh partials reduced through smem in the gate phase.
// ---------------------------------------------------------------------------
__global__ void __launch_bounds__(768, 1) gru_kernel(
    const float* __restrict__ Whh, const float* __restrict__ bhh,
    float* __restrict__ out)
{
    extern __shared__ char smraw[];
    ull*   wdup = reinterpret_cast<ull*>(smraw);           // 192*64 ull = 98304B
    float* h_s  = reinterpret_cast<float*>(smraw + 98304); // 64*20 = 5120B  [k][s]
    float* gx_s = h_s + 64 * 20;                           // 192*18 = 13824B [j][s]
    ull*   gh_s = reinterpret_cast<ull*>(smraw + 98304 + 5120 + 13824); // 192*2*2*4 ull = 24576B
    // total 141824 B

    const int tid = threadIdx.x;
    const int kq  = tid & 1;            // k half: k in [kq*32, kq*32+32)
    const int sp  = (tid >> 1) & 1;     // stock octet: stocks 8sp..8sp+7
    const int gj  = tid >> 2;           // 0..191 = gate*64 + j
    const int s0  = blockIdx.x * 16;

    // Stage pre-duplicated weights: wdup[gj*64+k] = (w,w)
    for (int i = tid; i < 12288; i += 768) wdup[i] = dup2(__ldg(&Whh[i]));
    for (int i = tid; i < 64 * 20; i += 768) h_s[i] = 0.0f;

    const ull bb = (kq == 0) ? dup2(__ldg(&bhh[gj])) : 0ULL;
    __syncthreads();

    const ull*   wp = wdup + gj * 64 + kq * 32;
    const float* hp = h_s + kq * 32 * 20 + 8 * sp;
    ull* ghme = gh_s + ((gj * 2 + sp) * 2 + kq) * 4;

    for (int t = 0; t < T_DIM; t++) {
        // Prefetch this step's gx tile (coalesced; hidden under the GEMM)
        float gbuf[4];
        #pragma unroll
        for (int i = 0; i < 4; i++) {
            int idx = tid + 768 * i;              // 3072 = 192*16
            int jj = idx >> 4, ss = idx & 15;
            gbuf[i] = __ldg(&g_gx[((size_t)t * G3 + jj) * S_DIM + s0 + ss]);
        }

        // Partial gh over 32 k's for (gj, stocks 8sp..8sp+7)
        ull a0 = bb, a1 = bb, a2 = bb, a3 = bb;
        #pragma unroll
        for (int k = 0; k < 32; k++) {
            ull w = wp[k];
            ulonglong2 hA = *reinterpret_cast<const ulonglong2*>(hp + k * 20);
            ulonglong2 hB = *reinterpret_cast<const ulonglong2*>(hp + k * 20 + 4);
            fma2(a0, hA.x, w);
            fma2(a1, hA.y, w);
            fma2(a2, hB.x, w);
            fma2(a3, hB.y, w);
        }
        *reinterpret_cast<ulonglong2*>(ghme)     = make_ulonglong2(a0, a1);
        *reinterpret_cast<ulonglong2*>(ghme + 2) = make_ulonglong2(a2, a3);

        // Stage gx into shared [j][s]
        #pragma unroll
        for (int i = 0; i < 4; i++) {
            int idx = tid + 768 * i;
            int jj = idx >> 4, ss = idx & 15;
            gx_s[jj * 18 + ss] = gbuf[i];
        }
        __syncthreads();   // gh partials + gx visible; GEMM reads of old h done

        // Gate math: element-pair q = (j 0..63, stockpair spg 0..7), 512 total
        if (tid < 512) {
            const int spg = tid & 7;           // stocks 2spg, 2spg+1
            const int jq  = tid >> 3;
            const int sq  = spg >> 2;          // which sp octet
            const int pi  = spg & 3;           // pair within octet

            #define GH(g) ( ((((g)*64 + jq) * 2 + sq) * 2) * 4 + pi )
            float2 r0 = unpk(gh_s[GH(0)]),     r1 = unpk(gh_s[GH(0) + 4]);
            float2 z0 = unpk(gh_s[GH(1)]),     z1 = unpk(gh_s[GH(1) + 4]);
            float2 n0 = unpk(gh_s[GH(2)]),     n1 = unpk(gh_s[GH(2) + 4]);
            #undef GH
            float2 ar = make_float2(r0.x + r1.x, r0.y + r1.y);
            float2 az = make_float2(z0.x + z1.x, z0.y + z1.y);
            float2 an = make_float2(n0.x + n1.x, n0.y + n1.y);

            float2 gr = unpk(*reinterpret_cast<const ull*>(gx_s + jq * 18 + 2 * spg));
            float2 gz = unpk(*reinterpret_cast<const ull*>(gx_s + (64 + jq) * 18 + 2 * spg));
            float2 gn = unpk(*reinterpret_cast<const ull*>(gx_s + (128 + jq) * 18 + 2 * spg));
            float2 ho = unpk(*reinterpret_cast<const ull*>(h_s + jq * 20 + 2 * spg));

            float hn[2];
            #pragma unroll
            for (int e = 0; e < 2; e++) {
                float arv = e ? ar.y : ar.x, azv = e ? az.y : az.x, anv = e ? an.y : an.x;
                float grv = e ? gr.y : gr.x, gzv = e ? gz.y : gz.x, gnv = e ? gn.y : gn.x;
                float hov = e ? ho.y : ho.x;
                float rr = 1.0f / (1.0f + __expf(-(grv + arv)));
                float zz = 1.0f / (1.0f + __expf(-(gzv + azv)));
                float narg = gnv + rr * anv;
                float ex = __expf(-2.0f * fabsf(narg));
                float nn = (1.0f - ex) / (1.0f + ex);
                nn = copysignf(nn, narg);
                hn[e] = (1.0f - zz) * nn + zz * hov;
            }
            *reinterpret_cast<ull*>(h_s + jq * 20 + 2 * spg) = pack2(hn[0], hn[1]);
        }
        __syncthreads();   // new h visible before next step's GEMM
    }

    // Final hidden state: out[(s0+s)*64 + j]
    for (int idx = tid; idx < 1024; idx += 768) {
        int jj = idx & 63, ss = idx >> 6;
        out[(size_t)(s0 + ss) * L_DIM + jj] = h_s[jj * 20 + ss];
    }
}

// ---------------------------------------------------------------------------
extern "C" void kernel_launch(void* const* d_in, const int* in_sizes, int n_in,
                              void* d_out, int out_size)
{
    const float* x   = (const float*)d_in[0];
    const float* W1  = (const float*)d_in[1];
    const float* b1  = (const float*)d_in[2];
    const float* W2  = (const float*)d_in[3];
    const float* b2  = (const float*)d_in[4];
    const float* Wih = (const float*)d_in[5];
    const float* Whh = (const float*)d_in[6];
    const float* bih = (const float*)d_in[7];
    const float* bhh = (const float*)d_in[8];
    float* out = (float*)d_out;

    static bool attrs_set = false;
    if (!attrs_set) {
        cudaFuncSetAttribute(mlp_gx_kernel,
                             cudaFuncAttributeMaxDynamicSharedMemorySize, 27168 * 4);
        cudaFuncSetAttribute(gru_kernel,
                             cudaFuncAttributeMaxDynamicSharedMemorySize, 141824);
        attrs_set = true;
    }

    mlp_gx_kernel<<<2048, 256, 27168 * 4>>>(x, W1, b1, W2, b2, Wih, bih);
    gru_kernel<<<128, 768, 141824>>>(Whh, bhh, out);
}

// round 5
// speedup vs baseline: 1.8285x; 1.8285x over previous
#include <cuda_runtime.h>
#include <math.h>

#define T_DIM 256
#define S_DIM 2048
#define C_DIM 128
#define G3    192
#define L_DIM 64

typedef unsigned long long ull;

// Scratch gx = h_proj @ W_ih^T + b_ih, layout [t][j][s]
__device__ float g_gx[(size_t)T_DIM * G3 * S_DIM];

// ---- packed f32x2 helpers ----
__device__ __forceinline__ ull dup2(float x) {
    ull r; asm("mov.b64 %0, {%1, %1};" : "=l"(r) : "f"(x)); return r;
}
__device__ __forceinline__ ull pack2(float x, float y) {
    ull r; asm("mov.b64 %0, {%1, %2};" : "=l"(r) : "f"(x), "f"(y)); return r;
}
__device__ __forceinline__ void fma2(ull& d, ull a, ull b) {
    asm("fma.rn.f32x2 %0, %1, %2, %0;" : "+l"(d) : "l"(a), "l"(b));
}
__device__ __forceinline__ float2 unpk(ull v) {
    float2 f; asm("mov.b64 {%0, %1}, %2;" : "=f"(f.x), "=f"(f.y) : "l"(v)); return f;
}

// ---------------------------------------------------------------------------
// Phase 1: MLP (128->32->64, LeakyReLU) + gx projection (64->192), f32x2.
// (unchanged — ~630us)
// ---------------------------------------------------------------------------
__global__ void __launch_bounds__(256, 2) mlp_gx_kernel(
    const float* __restrict__ x,
    const float* __restrict__ W1, const float* __restrict__ b1,
    const float* __restrict__ W2, const float* __restrict__ b2,
    const float* __restrict__ Wih, const float* __restrict__ bih)
{
    extern __shared__ float sm[];
    float* W1s  = sm;                 // 4096
    float* W2s  = W1s  + 4096;        // 2048
    float* WihT = W2s  + 2048;        // 64*196 = 12544
    float* b1s  = WihT + 12544;       // 32
    float* b2s  = b1s  + 32;          // 64
    float* bihs = b2s  + 64;          // 192
    float* h1s  = bihs + 192;         // 32*256 = 8192  [k][tid]
    // total 27168 floats = 108672 B -> 2 blocks/SM

    const int tid = threadIdx.x;

    for (int i = tid; i < 4096; i += 256) W1s[i] = W1[i];
    for (int i = tid; i < 2048; i += 256) W2s[i] = W2[i];
    for (int i = tid; i < 12288; i += 256) {
        int j = i >> 6, k = i & 63;           // Wih is (192,64) row-major
        WihT[k * 196 + j] = Wih[i];
    }
    if (tid < 32)  b1s[tid] = b1[tid];
    if (tid < 64)  b2s[tid] = b2[tid];
    if (tid < 192) bihs[tid] = bih[tid];
    __syncthreads();

    const int row = blockIdx.x * 256 + tid;
    const int t = row >> 11;
    const int s = row & 2047;

    // ---- GEMM1: 128 -> 32 ----
    ull a1[16];
    {
        const ull* bp = reinterpret_cast<const ull*>(b1s);
        #pragma unroll
        for (int c = 0; c < 16; c++) a1[c] = bp[c];
    }
    const float4* xv = reinterpret_cast<const float4*>(x + (size_t)row * C_DIM);
    #pragma unroll 4
    for (int k4 = 0; k4 < 32; k4++) {
        float4 xq = __ldg(&xv[k4]);
        float xr[4] = {xq.x, xq.y, xq.z, xq.w};
        #pragma unroll
        for (int kk = 0; kk < 4; kk++) {
            ull xd = dup2(xr[kk]);
            const ulonglong2* w = reinterpret_cast<const ulonglong2*>(&W1s[(k4*4+kk) * 32]);
            #pragma unroll
            for (int c2 = 0; c2 < 8; c2++) {
                ulonglong2 wv = w[c2];
                fma2(a1[c2*2+0], xd, wv.x);
                fma2(a1[c2*2+1], xd, wv.y);
            }
        }
    }
    #pragma unroll
    for (int c = 0; c < 16; c++) {
        float2 f = unpk(a1[c]);
        h1s[(2*c+0) * 256 + tid] = fmaxf(f.x, 0.01f * f.x);
        h1s[(2*c+1) * 256 + tid] = fmaxf(f.y, 0.01f * f.y);
    }

    // ---- GEMM2: 32 -> 64 ----
    ull a2[32];
    {
        const ull* bp = reinterpret_cast<const ull*>(b2s);
        #pragma unroll
        for (int c = 0; c < 32; c++) a2[c] = bp[c];
    }
    #pragma unroll 4
    for (int k = 0; k < 32; k++) {
        ull hd = dup2(h1s[k * 256 + tid]);
        const ulonglong2* w = reinterpret_cast<const ulonglong2*>(&W2s[k * 64]);
        #pragma unroll
        for (int c2 = 0; c2 < 16; c2++) {
            ulonglong2 wv = w[c2];
            fma2(a2[c2*2+0], hd, wv.x);
            fma2(a2[c2*2+1], hd, wv.y);
        }
    }
    float h2[64];
    #pragma unroll
    for (int c = 0; c < 32; c++) {
        float2 f = unpk(a2[c]);
        h2[2*c+0] = fmaxf(f.x, 0.01f * f.x);
        h2[2*c+1] = fmaxf(f.y, 0.01f * f.y);
    }

    // ---- GEMM3: 64 -> 192 in 6 chunks of 32 ----
    float* gbase = &g_gx[(size_t)t * G3 * S_DIM + s];
    #pragma unroll 1
    for (int ch = 0; ch < 6; ch++) {
        const int j0 = ch * 32;
        ull acc[16];
        const ull* bp = reinterpret_cast<const ull*>(&bihs[j0]);
        #pragma unroll
        for (int c = 0; c < 16; c++) acc[c] = bp[c];

        #pragma unroll
        for (int k = 0; k < 64; k++) {
            ull hd = dup2(h2[k]);
            const ulonglong2* w = reinterpret_cast<const ulonglong2*>(&WihT[k * 196 + j0]);
            #pragma unroll
            for (int c2 = 0; c2 < 8; c2++) {
                ulonglong2 wv = w[c2];
                fma2(acc[c2*2+0], hd, wv.x);
                fma2(acc[c2*2+1], hd, wv.y);
            }
        }
        float* gd = gbase + (size_t)j0 * S_DIM;
        #pragma unroll
        for (int c = 0; c < 16; c++) {
            float2 f = unpk(acc[c]);
            gd[(size_t)(2*c+0) * S_DIM] = f.x;
            gd[(size_t)(2*c+1) * S_DIM] = f.y;
        }
    }
}

// ---------------------------------------------------------------------------
// Phase 2: GRU. 128 blocks x 768 threads (24 warps/SM), 16 stocks/block.
// Thread = (gj 0..191, sp 0..1, kq 0..1): tid = gj*4 + sp*2 + kq.
// Weights in smem, CONFLICT-FREE swizzle (stride 70/33 -> banks 12gj+2kq:
// 16 distinct 8B words per warp hit all 32 banks once = 1 wavefront).
// h padded so the kq halves land on disjoint banks. kq-partials reduced via
// shfl.xor(1); only kq=0 lanes store gh (transposed layout, STS.64).
// ---------------------------------------------------------------------------
__global__ void __launch_bounds__(768, 1) gru_kernel(
    const float* __restrict__ Whh, const float* __restrict__ bhh,
    float* __restrict__ out)
{
    extern __shared__ char smraw[];
    ull*   wdup = reinterpret_cast<ull*>(smraw);              // 192*70 ull = 107520B
    float* h_s  = reinterpret_cast<float*>(smraw + 107520);   // 64*20+4 = 5136B
    float* gx_s = h_s + (64 * 20 + 4);                        // 192*18 = 13824B
    ull*   gh_s = reinterpret_cast<ull*>(smraw + 107520 + 5136 + 13824); // 4*392 ull = 12544B
    // total 139024 B

    const int tid = threadIdx.x;
    const int kq  = tid & 1;            // k half: [kq*32, kq*32+32)
    const int sp  = (tid >> 1) & 1;     // stock octet: stocks 8sp..8sp+7
    const int gj  = tid >> 2;           // 0..191 = gate*64 + j
    const int s0  = blockIdx.x * 16;

    // Stage weights with bank swizzle: wdup[gj*70 + (k>=32)*33 + (k&31)]
    for (int i = tid; i < 12288; i += 768) {
        int g = i >> 6, k = i & 63;
        wdup[g * 70 + (k >> 5) * 33 + (k & 31)] = dup2(__ldg(&Whh[i]));
    }
    for (int i = tid; i < 64 * 20 + 4; i += 768) h_s[i] = 0.0f;

    const ull bb = (kq == 0) ? dup2(__ldg(&bhh[gj])) : 0ULL;
    __syncthreads();

    const ull*   wp = wdup + gj * 70 + kq * 33;
    const float* hp = h_s + kq * 644 + 8 * sp;   // kq half padded by +4 floats
    const int slot2 = gj * 2 + sp;               // 0..383

    for (int t = 0; t < T_DIM; t++) {
        // Prefetch this step's gx tile (coalesced; hidden under the GEMM)
        float gbuf[4];
        #pragma unroll
        for (int i = 0; i < 4; i++) {
            int idx = tid + 768 * i;              // 3072 = 192*16
            int jj = idx >> 4, ss = idx & 15;
            gbuf[i] = __ldg(&g_gx[((size_t)t * G3 + jj) * S_DIM + s0 + ss]);
        }

        // Partial gh over 32 k's for (gj, stocks 8sp..8sp+7)
        ull a0 = bb, a1 = bb, a2 = bb, a3 = bb;
        #pragma unroll
        for (int k = 0; k < 32; k++) {
            ull w = wp[k];
            ulonglong2 hA = *reinterpret_cast<const ulonglong2*>(hp + k * 20);
            ulonglong2 hB = *reinterpret_cast<const ulonglong2*>(hp + k * 20 + 4);
            fma2(a0, hA.x, w);
            fma2(a1, hA.y, w);
            fma2(a2, hB.x, w);
            fma2(a3, hB.y, w);
        }

        // Reduce kq partials via shfl (kq = tid bit 0)
        float2 f0 = unpk(a0), f1 = unpk(a1), f2 = unpk(a2), f3 = unpk(a3);
        f0.x += __shfl_xor_sync(0xFFFFFFFFu, f0.x, 1);
        f0.y += __shfl_xor_sync(0xFFFFFFFFu, f0.y, 1);
        f1.x += __shfl_xor_sync(0xFFFFFFFFu, f1.x, 1);
        f1.y += __shfl_xor_sync(0xFFFFFFFFu, f1.y, 1);
        f2.x += __shfl_xor_sync(0xFFFFFFFFu, f2.x, 1);
        f2.y += __shfl_xor_sync(0xFFFFFFFFu, f2.y, 1);
        f3.x += __shfl_xor_sync(0xFFFFFFFFu, f3.x, 1);
        f3.y += __shfl_xor_sync(0xFFFFFFFFu, f3.y, 1);
        if (kq == 0) {
            gh_s[0 * 392 + slot2] = pack2(f0.x, f0.y);
            gh_s[1 * 392 + slot2] = pack2(f1.x, f1.y);
            gh_s[2 * 392 + slot2] = pack2(f2.x, f2.y);
            gh_s[3 * 392 + slot2] = pack2(f3.x, f3.y);
        }

        // Stage gx into shared [j][s]
        #pragma unroll
        for (int i = 0; i < 4; i++) {
            int idx = tid + 768 * i;
            int jj = idx >> 4, ss = idx & 15;
            gx_s[jj * 18 + ss] = gbuf[i];
        }
        __syncthreads();   // gh + gx visible; GEMM reads of old h done

        // Gate math: element-pair q = (j 0..63, stockpair spg 0..7), 512 total
        if (tid < 512) {
            const int spg = tid & 7;           // stocks 2spg, 2spg+1
            const int jq  = tid >> 3;
            const int sq  = spg >> 2;          // which sp octet
            const int pi  = spg & 3;           // pair within octet

            float2 ar = unpk(gh_s[pi * 392 + (          jq) * 2 + sq]);
            float2 az = unpk(gh_s[pi * 392 + ( 64 + jq) * 2 + sq]);
            float2 an = unpk(gh_s[pi * 392 + (128 + jq) * 2 + sq]);

            float2 gr = unpk(*reinterpret_cast<const ull*>(gx_s + jq * 18 + 2 * spg));
            float2 gz = unpk(*reinterpret_cast<const ull*>(gx_s + (64 + jq) * 18 + 2 * spg));
            float2 gn = unpk(*reinterpret_cast<const ull*>(gx_s + (128 + jq) * 18 + 2 * spg));

            const int hoff = jq * 20 + (jq >> 5) * 4 + 2 * spg;
            float2 ho = unpk(*reinterpret_cast<const ull*>(h_s + hoff));

            float hn[2];
            #pragma unroll
            for (int e = 0; e < 2; e++) {
                float arv = e ? ar.y : ar.x, azv = e ? az.y : az.x, anv = e ? an.y : an.x;
                float grv = e ? gr.y : gr.x, gzv = e ? gz.y : gz.x, gnv = e ? gn.y : gn.x;
                float hov = e ? ho.y : ho.x;
                float rr = 1.0f / (1.0f + __expf(-(grv + arv)));
                float zz = 1.0f / (1.0f + __expf(-(gzv + azv)));
                float narg = gnv + rr * anv;
                float ex = __expf(-2.0f * fabsf(narg));
                float nn = (1.0f - ex) / (1.0f + ex);
                nn = copysignf(nn, narg);
                hn[e] = (1.0f - zz) * nn + zz * hov;
            }
            *reinterpret_cast<ull*>(h_s + hoff) = pack2(hn[0], hn[1]);
        }
        __syncthreads();   // new h visible before next step's GEMM
    }

    // Final hidden state: out[(s0+s)*64 + j]
    for (int idx = tid; idx < 1024; idx += 768) {
        int jj = idx & 63, ss = idx >> 6;
        out[(size_t)(s0 + ss) * L_DIM + jj] = h_s[jj * 20 + (jj >> 5) * 4 + ss];
    }
}

// ---------------------------------------------------------------------------
extern "C" void kernel_launch(void* const* d_in, const int* in_sizes, int n_in,
                              void* d_out, int out_size)
{
    const float* x   = (const float*)d_in[0];
    const float* W1  = (const float*)d_in[1];
    const float* b1  = (const float*)d_in[2];
    const float* W2  = (const float*)d_in[3];
    const float* b2  = (const float*)d_in[4];
    const float* Wih = (const float*)d_in[5];
    const float* Whh = (const float*)d_in[6];
    const float* bih = (const float*)d_in[7];
    const float* bhh = (const float*)d_in[8];
    float* out = (float*)d_out;

    static bool attrs_set = false;
    if (!attrs_set) {
        cudaFuncSetAttribute(mlp_gx_kernel,
                             cudaFuncAttributeMaxDynamicSharedMemorySize, 27168 * 4);
        cudaFuncSetAttribute(gru_kernel,
                             cudaFuncAttributeMaxDynamicSharedMemorySize, 139024);
        attrs_set = true;
    }

    mlp_gx_kernel<<<2048, 256, 27168 * 4>>>(x, W1, b1, W2, b2, Wih, bih);
    gru_kernel<<<128, 768, 139024>>>(Whh, bhh, out);
}